// round 2
// baseline (speedup 1.0000x reference)
#include <cuda_runtime.h>
#include <math.h>

#define N_MAX    262144
#define DNUM     4
#define FDIM     100
#define F2       200
#define HDIM     128
#define TILE_M   128
#define KC       32
#define NTHREADS 256
#define TWO_PI_F 6.2831853071795864769f

// Scratch (allocation-free): per-domain compacted point indices.
__device__ int g_counts[DNUM];
__device__ int g_idx[DNUM * N_MAX];

__global__ void zero_counts_kernel() {
    if (threadIdx.x < DNUM) g_counts[threadIdx.x] = 0;
}

__global__ void bucket_kernel(const float* __restrict__ x, int n) {
    int i = blockIdx.x * blockDim.x + threadIdx.x;
    if (i >= n) return;
    float xv = x[i];
    // interfaces: [-0.5, 0.0, 0.5]; masks (x>=lo)&(x<hi) partition the line
    int d = (xv < -0.5f) ? 0 : (xv < 0.0f) ? 1 : (xv < 0.5f) ? 2 : 3;
    int pos = atomicAdd(&g_counts[d], 1);
    g_idx[d * N_MAX + pos] = i;
}

__device__ __forceinline__ float silu_f(float v) {
    return v / (1.0f + __expf(-v));
}

// One GEMM layer: sOut[h][m] = silu( sum_k sIn[k][m] * W[k][h] + b[h] )
// sIn: [K][TILE_M] row-major in SMEM. W: [K][HDIM] row-major in GMEM (L2-resident).
// Thread map: tm = tid>>5 (16 rows: tm*16..+15), tn = tid&31 (4 cols: tn*4..+3).
__device__ __forceinline__ void gemm_layer(
    const float* __restrict__ sIn, int K,
    const float* __restrict__ Wg, const float* __restrict__ bg,
    float* __restrict__ sOut, float* __restrict__ sW, float* __restrict__ sBias,
    int tid)
{
    if (tid < HDIM) sBias[tid] = bg[tid];

    const int tm = tid >> 5;
    const int tn = tid & 31;
    const int row0 = tm * 16;
    const int col0 = tn * 4;

    float acc[16][4];
#pragma unroll
    for (int r = 0; r < 16; r++)
#pragma unroll
        for (int c = 0; c < 4; c++) acc[r][c] = 0.0f;

    for (int k0 = 0; k0 < K; k0 += KC) {
        const int kcnt = (K - k0 < KC) ? (K - k0) : KC;
        __syncthreads();  // previous chunk fully consumed before overwriting sW
        // Stage W chunk [kcnt][128] into SMEM (contiguous, coalesced, float4)
        {
            const float4* Wg4 = (const float4*)(Wg + (size_t)k0 * HDIM);
            const int nv = kcnt * (HDIM / 4);
            for (int v = tid; v < nv; v += NTHREADS) ((float4*)sW)[v] = Wg4[v];
        }
        __syncthreads();

        // Inner product over this K chunk
        auto body = [&](int kk) {
            float4 bv = *(const float4*)(sW + kk * HDIM + col0);
            float bc[4] = {bv.x, bv.y, bv.z, bv.w};
            const float* ar = sIn + (size_t)(k0 + kk) * TILE_M + row0;
#pragma unroll
            for (int j = 0; j < 4; j++) {
                float4 av = *(const float4*)(ar + 4 * j);
                float ac[4] = {av.x, av.y, av.z, av.w};
#pragma unroll
                for (int rr = 0; rr < 4; rr++)
#pragma unroll
                    for (int c = 0; c < 4; c++)
                        acc[4 * j + rr][c] += ac[rr] * bc[c];
            }
        };
        if (kcnt == KC) {
#pragma unroll 4
            for (int kk = 0; kk < KC; kk++) body(kk);
        } else {
            for (int kk = 0; kk < kcnt; kk++) body(kk);
        }
    }
    __syncthreads();

    // Bias + SiLU + store transposed [h][m]
#pragma unroll
    for (int c = 0; c < 4; c++) {
        float bb = sBias[col0 + c];
        float* op = sOut + (size_t)(col0 + c) * TILE_M + row0;
#pragma unroll
        for (int r = 0; r < 16; r += 4) {
            float4 v;
            v.x = silu_f(acc[r + 0][c] + bb);
            v.y = silu_f(acc[r + 1][c] + bb);
            v.z = silu_f(acc[r + 2][c] + bb);
            v.w = silu_f(acc[r + 3][c] + bb);
            *(float4*)(op + r) = v;
        }
    }
    __syncthreads();
}

// SMEM layout (floats):
//   sA    [F2][TILE_M]   = 25600   (activations A / ping)
//   sH    [HDIM][TILE_M] = 16384   (activations B / pong)
//   sW    [KC][HDIM]     = 4096    (weight chunk)
//   sB    [F2]           = 200     (Fourier B for this domain, [f][2] flat)
//   sBias [HDIM]         = 128
//   sX    [TILE_M]       = 128
//   sT    [TILE_M]       = 128
//   sIdx  [TILE_M] (int) = 128
#define SMEM_FLOATS (25600 + 16384 + 4096 + 200 + 128 + 128 + 128 + 128)
#define SMEM_BYTES  (SMEM_FLOATS * 4)

__global__ void __launch_bounds__(NTHREADS, 1) xpinn_main_kernel(
    const float* __restrict__ x, const float* __restrict__ t,
    const float* __restrict__ Bf,
    const float* __restrict__ W1, const float* __restrict__ b1,
    const float* __restrict__ W2, const float* __restrict__ b2,
    const float* __restrict__ W3, const float* __restrict__ b3,
    const float* __restrict__ W4, const float* __restrict__ b4,
    float* __restrict__ out)
{
    const int dom  = blockIdx.y;
    const int base = blockIdx.x * TILE_M;
    const int cnt  = g_counts[dom];
    if (base >= cnt) return;

    extern __shared__ __align__(16) float smem[];
    float* sA    = smem;
    float* sH    = sA + F2 * TILE_M;
    float* sW    = sH + HDIM * TILE_M;
    float* sB    = sW + KC * HDIM;
    float* sBias = sB + F2;
    float* sX    = sBias + HDIM;
    float* sT    = sX + TILE_M;
    int*   sIdx  = (int*)(sT + TILE_M);

    const int tid = threadIdx.x;
    const int nm  = (cnt - base < TILE_M) ? (cnt - base) : TILE_M;

    // Gather point coords for this tile
    if (tid < TILE_M) {
        if (tid < nm) {
            int i = g_idx[dom * N_MAX + base + tid];
            sIdx[tid] = i;
            sX[tid] = x[i];
            sT[tid] = t[i];
        } else {
            sIdx[tid] = -1;
            sX[tid] = 0.0f;
            sT[tid] = 0.0f;
        }
    }
    if (tid < F2) sB[tid] = Bf[dom * F2 + tid];
    __syncthreads();

    // Fourier features, transposed: sA[f][m] = sin, sA[f+F][m] = cos
    for (int lin = tid; lin < TILE_M * FDIM; lin += NTHREADS) {
        int m = lin & (TILE_M - 1);
        int f = lin >> 7;  // TILE_M == 128
        float pr = TWO_PI_F * (sX[m] * sB[2 * f] + sT[m] * sB[2 * f + 1]);
        float s, c;
        sincosf(pr, &s, &c);
        sA[f * TILE_M + m]          = s;
        sA[(f + FDIM) * TILE_M + m] = c;
    }
    __syncthreads();

    // MLP: ping-pong between sA and sH
    gemm_layer(sA, F2,   W1 + (size_t)dom * F2 * HDIM,   b1 + dom * HDIM, sH, sW, sBias, tid);
    gemm_layer(sH, HDIM, W2 + (size_t)dom * HDIM * HDIM, b2 + dom * HDIM, sA, sW, sBias, tid);
    gemm_layer(sA, HDIM, W3 + (size_t)dom * HDIM * HDIM, b3 + dom * HDIM, sH, sW, sBias, tid);

    // Final 128 -> 1 head, scatter to output
    if (tid < HDIM) sW[tid] = W4[dom * HDIM + tid];
    __syncthreads();
    if (tid < nm) {
        float u = b4[dom];
#pragma unroll 8
        for (int k = 0; k < HDIM; k++) u += sH[k * TILE_M + tid] * sW[k];
        out[sIdx[tid]] = u;
    }
}

extern "C" void kernel_launch(void* const* d_in, const int* in_sizes, int n_in,
                              void* d_out, int out_size)
{
    const float* x  = (const float*)d_in[0];
    const float* t  = (const float*)d_in[1];
    const float* Bf = (const float*)d_in[2];
    const float* W1 = (const float*)d_in[3];
    const float* b1 = (const float*)d_in[4];
    const float* W2 = (const float*)d_in[5];
    const float* b2 = (const float*)d_in[6];
    const float* W3 = (const float*)d_in[7];
    const float* b3 = (const float*)d_in[8];
    const float* W4 = (const float*)d_in[9];
    const float* b4 = (const float*)d_in[10];
    float* out = (float*)d_out;
    const int n = in_sizes[0];

    (void)n_in; (void)out_size;

    cudaFuncSetAttribute(xpinn_main_kernel,
                         cudaFuncAttributeMaxDynamicSharedMemorySize, SMEM_BYTES);

    zero_counts_kernel<<<1, 32>>>();
    bucket_kernel<<<(n + 255) / 256, 256>>>(x, n);

    dim3 grid((n + TILE_M - 1) / TILE_M, DNUM);
    xpinn_main_kernel<<<grid, NTHREADS, SMEM_BYTES>>>(
        x, t, Bf, W1, b1, W2, b2, W3, b3, W4, b4, out);
}

// round 4
// speedup vs baseline: 2.0550x; 2.0550x over previous
#include <cuda_runtime.h>
#include <cuda_fp16.h>
#include <math.h>
#include <stdint.h>

#define DNUM   4
#define N_MAX  262144
#define FDIM   100
#define HDIM   128
#define TILE_M 128
#define NT     256
#define TWO_PI_F 6.2831853071795864769f

// ---------------- device scratch (allocation-free) ----------------
__device__ int g_counts[DNUM];
__device__ int g_idx[DNUM * N_MAX];
// Pre-split (f16 hi/lo), transposed [n][k], XOR-swizzled weight images, 32KB each.
__device__ __align__(16) uint8_t g_w1_hi[DNUM][2][32768];
__device__ __align__(16) uint8_t g_w1_lo[DNUM][2][32768];
__device__ __align__(16) uint8_t g_w2_hi[DNUM][32768];
__device__ __align__(16) uint8_t g_w2_lo[DNUM][32768];
__device__ __align__(16) uint8_t g_w3_hi[DNUM][32768];
__device__ __align__(16) uint8_t g_w3_lo[DNUM][32768];

// swizzled byte offset inside a [128 rows][128 cols-f16] image (256B rows)
__device__ __host__ __forceinline__ int sw_off(int row, int col) {
    return row * 256 + ((((col >> 3) ^ (row & 7)) << 4)) + ((col & 7) << 1);
}

// ---------------- prep kernels ----------------
__global__ void zero_counts_kernel() {
    if (threadIdx.x < DNUM) g_counts[threadIdx.x] = 0;
}
__global__ void bucket_kernel(const float* __restrict__ x, int n) {
    int i = blockIdx.x * blockDim.x + threadIdx.x;
    if (i >= n) return;
    float xv = x[i];
    int d = (xv < -0.5f) ? 0 : (xv < 0.0f) ? 1 : (xv < 0.5f) ? 2 : 3;
    int pos = atomicAdd(&g_counts[d], 1);
    g_idx[d * N_MAX + pos] = i;
}

// W1 col j (0..255): f=j>>1, s=j&1 -> W1 row f+100s (f>=100 pad 0). W2/W3 direct.
__global__ void prep_weights_kernel(const float* __restrict__ W1,
                                    const float* __restrict__ W2,
                                    const float* __restrict__ W3) {
    const int T1 = DNUM * 2 * HDIM * HDIM;   // both chunks
    const int T2 = DNUM * HDIM * HDIM;
    int idx = blockIdx.x * blockDim.x + threadIdx.x;
    float w; uint8_t *hiA, *loA; int off;
    if (idx < T1) {
        int d = idx / (2 * HDIM * HDIM), r = idx % (2 * HDIM * HDIM);
        int c = r / (HDIM * HDIM), r2 = r % (HDIM * HDIM);
        int k = r2 / HDIM, n = r2 % HDIM;
        int j = c * 128 + k, f = j >> 1, s = j & 1;
        w = (f < FDIM) ? W1[((size_t)d * 2 * FDIM + (f + FDIM * s)) * HDIM + n] : 0.0f;
        off = sw_off(n, k); hiA = g_w1_hi[d][c]; loA = g_w1_lo[d][c];
    } else if (idx < T1 + T2) {
        int r0 = idx - T1;
        int d = r0 / (HDIM * HDIM), r2 = r0 % (HDIM * HDIM);
        int k = r2 / HDIM, n = r2 % HDIM;
        w = W2[((size_t)d * HDIM + k) * HDIM + n];
        off = sw_off(n, k); hiA = g_w2_hi[d]; loA = g_w2_lo[d];
    } else if (idx < T1 + 2 * T2) {
        int r0 = idx - T1 - T2;
        int d = r0 / (HDIM * HDIM), r2 = r0 % (HDIM * HDIM);
        int k = r2 / HDIM, n = r2 % HDIM;
        w = W3[((size_t)d * HDIM + k) * HDIM + n];
        off = sw_off(n, k); hiA = g_w3_hi[d]; loA = g_w3_lo[d];
    } else return;
    __half hi = __float2half_rn(w);
    __half lo = __float2half_rn(w - __half2float(hi));
    *(__half*)(hiA + off) = hi;
    *(__half*)(loA + off) = lo;
}

// ---------------- asm helpers (all plain-sm_103-legal) ----------------
__device__ __forceinline__ uint32_t smem_u32(const void* p) {
    uint32_t a;
    asm("{ .reg .u64 t; cvta.to.shared.u64 t, %1; cvt.u32.u64 %0, t; }" : "=r"(a) : "l"(p));
    return a;
}
__device__ __forceinline__ void ldsm_x4(uint32_t* r, uint32_t addr) {
    asm volatile("ldmatrix.sync.aligned.m8n8.x4.shared.b16 {%0,%1,%2,%3}, [%4];"
        : "=r"(r[0]), "=r"(r[1]), "=r"(r[2]), "=r"(r[3]) : "r"(addr));
}
__device__ __forceinline__ void ldsm_x2(uint32_t* r, uint32_t addr) {
    asm volatile("ldmatrix.sync.aligned.m8n8.x2.shared.b16 {%0,%1}, [%2];"
        : "=r"(r[0]), "=r"(r[1]) : "r"(addr));
}
__device__ __forceinline__ void mma16816(float* d, const uint32_t* a, const uint32_t* b) {
    asm volatile("mma.sync.aligned.m16n8k16.row.col.f32.f16.f16.f32 "
        "{%0,%1,%2,%3}, {%4,%5,%6,%7}, {%8,%9}, {%0,%1,%2,%3};"
        : "+f"(d[0]), "+f"(d[1]), "+f"(d[2]), "+f"(d[3])
        : "r"(a[0]), "r"(a[1]), "r"(a[2]), "r"(a[3]), "r"(b[0]), "r"(b[1]));
}
#define CP_COMMIT() asm volatile("cp.async.commit_group;" ::: "memory")
#define CP_WAIT(n)  asm volatile("cp.async.wait_group %0;" :: "n"(n) : "memory")
__device__ __forceinline__ void cp_issue32k(uint32_t smem_dst, const uint8_t* gsrc, int tid) {
#pragma unroll
    for (int i = 0; i < 8; i++) {
        int off = (tid + i * NT) * 16;
        asm volatile("cp.async.cg.shared.global [%0], [%1], 16;"
            :: "r"(smem_dst + off), "l"(gsrc + off) : "memory");
    }
}

// ---------------- SMEM layout (bytes) ----------------
#define S_P_HI   0
#define S_P_LO   32768
#define S_W_HI0  65536
#define S_W_LO0  98304
#define S_W_HI1  131072
#define S_W_LO1  163840
#define S_MISC   196608
#define MS_BX    0        // 128 f32
#define MS_BT    512
#define MS_B1    1024
#define MS_B2    1536
#define MS_B3    2048
#define MS_W4    2560
#define MS_X     3072
#define MS_T     3584
#define MS_IDX   4096
#define MS_PART  4608     // 2 x 128 f32
#define SMEM_TOTAL (S_MISC + 5632)

__device__ __forceinline__ float silu_f(float v) { return v / (1.0f + __expf(-v)); }
__device__ __forceinline__ uint32_t pack2(float a, float b) {
    __half2 h = __halves2half2(__float2half_rn(a), __float2half_rn(b));
    return *(uint32_t*)&h;
}
__device__ __forceinline__ uint32_t pack2lo(float a, float b) {
    // residuals after f16 rounding
    float ar = a - __half2float(__float2half_rn(a));
    float br = b - __half2float(__float2half_rn(b));
    return pack2(ar, br);
}

// One K=128 MMA pass: acc += A(P) * W(stage)
__device__ __forceinline__ void mma_pass(float acc[2][8][4], uint32_t base,
                                         uint32_t wHi, uint32_t wLo,
                                         int m0, int n0, int lane) {
    const int a_rowl = ((lane >> 3) & 1) * 8 + (lane & 7);
    const int a_k8   = (lane >> 4) & 1;           // +8 k for matrices 2,3
    const int b_k8   = (lane >> 3) & 1;
    const int l7     = lane & 7;
    for (int ks = 0; ks < 8; ks++) {
        uint32_t aH[2][4], aL[2][4];
        int swzA = ((ks * 2 + a_k8) ^ l7) << 4;
#pragma unroll
        for (int t = 0; t < 2; t++) {
            uint32_t rb = (uint32_t)(m0 + t * 16 + a_rowl) * 256 + swzA;
            ldsm_x4(aH[t], base + S_P_HI + rb);
            ldsm_x4(aL[t], base + S_P_LO + rb);
        }
        int swzB = ((ks * 2 + b_k8) ^ l7) << 4;
#pragma unroll
        for (int u = 0; u < 8; u++) {
            uint32_t rb = (uint32_t)(n0 + u * 8 + l7) * 256 + swzB;
            uint32_t bh[2], bl[2];
            ldsm_x2(bh, base + wHi + rb);
            ldsm_x2(bl, base + wLo + rb);
            mma16816(acc[0][u], aH[0], bh);
            mma16816(acc[1][u], aH[1], bh);
            mma16816(acc[0][u], aL[0], bh);
            mma16816(acc[1][u], aL[1], bh);
            mma16816(acc[0][u], aH[0], bl);
            mma16816(acc[1][u], aH[1], bl);
        }
    }
}

// bias+SiLU, split to f16 hi/lo, store in place into P as next layer's A; zero acc
__device__ __forceinline__ void epilogue(float acc[2][8][4], char* smem,
                                         const float* bias, int m0, int n0, int lane) {
    const int lr = lane >> 2, lc = (lane & 3) * 2;
#pragma unroll
    for (int t = 0; t < 2; t++)
#pragma unroll
        for (int u = 0; u < 8; u++) {
            int n_ = n0 + u * 8 + lc;
            float b0 = bias[n_], b1v = bias[n_ + 1];
            float v0 = silu_f(acc[t][u][0] + b0);
            float v1 = silu_f(acc[t][u][1] + b1v);
            float v2 = silu_f(acc[t][u][2] + b0);
            float v3 = silu_f(acc[t][u][3] + b1v);
            acc[t][u][0] = acc[t][u][1] = acc[t][u][2] = acc[t][u][3] = 0.0f;
            int mA = m0 + t * 16 + lr;
            int chunk = (n_ >> 3) ^ (lr & 7);
            uint32_t addrA = (uint32_t)mA * 256 + (chunk << 4) + lc * 2;
            *(uint32_t*)(smem + S_P_HI + addrA) = pack2(v0, v1);
            *(uint32_t*)(smem + S_P_LO + addrA) = pack2lo(v0, v1);
            uint32_t addrB = addrA + 8 * 256;
            *(uint32_t*)(smem + S_P_HI + addrB) = pack2(v2, v3);
            *(uint32_t*)(smem + S_P_LO + addrB) = pack2lo(v2, v3);
        }
}

// Fourier features for one K=128 chunk into P (hi/lo)
__device__ __forceinline__ void gen_feats(char* smem, const float* sBx, const float* sBt,
                                          const float* sX, const float* sT,
                                          int chunk, int tid) {
    const int m = tid >> 1, half = tid & 1;
    const float xv = sX[m], tv = sT[m];
    const int fbase = chunk * 64 + half * 32;
#pragma unroll
    for (int g = 0; g < 8; g++) {
        uint32_t hi4[4], lo4[4];
#pragma unroll
        for (int i = 0; i < 4; i++) {
            int f = fbase + g * 4 + i;
            float s = 0.0f, c = 0.0f;
            if (f < FDIM) {
                float pr = TWO_PI_F * (xv * sBx[f] + tv * sBt[f]);
                __sincosf(pr, &s, &c);
            }
            hi4[i] = pack2(s, c);
            lo4[i] = pack2lo(s, c);
        }
        int c0 = half * 64 + g * 8;
        uint32_t addr = (uint32_t)m * 256 + ((((c0 >> 3) ^ (m & 7)) << 4));
        *(uint4*)(smem + S_P_HI + addr) = make_uint4(hi4[0], hi4[1], hi4[2], hi4[3]);
        *(uint4*)(smem + S_P_LO + addr) = make_uint4(lo4[0], lo4[1], lo4[2], lo4[3]);
    }
}

__global__ void __launch_bounds__(NT, 1) xpinn_mma_kernel(
    const float* __restrict__ x, const float* __restrict__ t,
    const float* __restrict__ Bf,
    const float* __restrict__ b1, const float* __restrict__ b2,
    const float* __restrict__ b3,
    const float* __restrict__ W4, const float* __restrict__ b4,
    float* __restrict__ out) {
    const int dom = blockIdx.y;
    const int base_pt = blockIdx.x * TILE_M;
    const int cnt = g_counts[dom];
    if (base_pt >= cnt) return;

    extern __shared__ __align__(16) char smem[];
    const uint32_t sb = smem_u32(smem);
    const int tid = threadIdx.x;
    const int wid = tid >> 5, lane = tid & 31;
    const int m0 = (wid >> 1) * 32, n0 = (wid & 1) * 64, nw = wid & 1;
    const int nm = (cnt - base_pt < TILE_M) ? (cnt - base_pt) : TILE_M;

    float* sBx = (float*)(smem + S_MISC + MS_BX);
    float* sBt = (float*)(smem + S_MISC + MS_BT);
    float* sB1 = (float*)(smem + S_MISC + MS_B1);
    float* sB2 = (float*)(smem + S_MISC + MS_B2);
    float* sB3 = (float*)(smem + S_MISC + MS_B3);
    float* sW4 = (float*)(smem + S_MISC + MS_W4);
    float* sX  = (float*)(smem + S_MISC + MS_X);
    float* sT  = (float*)(smem + S_MISC + MS_T);
    int*   sIdx = (int*)(smem + S_MISC + MS_IDX);
    float* sPart = (float*)(smem + S_MISC + MS_PART);

    // Prefetch W1 both chunks (G1: stage0, G2: stage1)
    cp_issue32k(sb + S_W_HI0, g_w1_hi[dom][0], tid);
    cp_issue32k(sb + S_W_LO0, g_w1_lo[dom][0], tid);
    CP_COMMIT();
    cp_issue32k(sb + S_W_HI1, g_w1_hi[dom][1], tid);
    cp_issue32k(sb + S_W_LO1, g_w1_lo[dom][1], tid);
    CP_COMMIT();

    if (tid < TILE_M) {
        if (tid < nm) {
            int i = g_idx[dom * N_MAX + base_pt + tid];
            sIdx[tid] = i; sX[tid] = x[i]; sT[tid] = t[i];
        } else { sIdx[tid] = -1; sX[tid] = 0.0f; sT[tid] = 0.0f; }
        sBx[tid] = (tid < FDIM) ? Bf[(dom * FDIM + tid) * 2]     : 0.0f;
        sBt[tid] = (tid < FDIM) ? Bf[(dom * FDIM + tid) * 2 + 1] : 0.0f;
        sB1[tid] = b1[dom * HDIM + tid];
        sB2[tid] = b2[dom * HDIM + tid];
        sB3[tid] = b3[dom * HDIM + tid];
        sW4[tid] = W4[dom * HDIM + tid];
    }
    __syncthreads();

    float acc[2][8][4];
#pragma unroll
    for (int t2 = 0; t2 < 2; t2++)
#pragma unroll
        for (int u = 0; u < 8; u++)
#pragma unroll
            for (int r = 0; r < 4; r++) acc[t2][u][r] = 0.0f;

    // ---- layer 1, K chunk 0 ----
    gen_feats(smem, sBx, sBt, sX, sT, 0, tid);
    CP_WAIT(1);
    __syncthreads();
    mma_pass(acc, sb, S_W_HI0, S_W_LO0, m0, n0, lane);
    __syncthreads();
    // ---- layer 1, K chunk 1 (feats in place; W2 -> stage0) ----
    gen_feats(smem, sBx, sBt, sX, sT, 1, tid);
    cp_issue32k(sb + S_W_HI0, g_w2_hi[dom], tid);
    cp_issue32k(sb + S_W_LO0, g_w2_lo[dom], tid);
    CP_COMMIT();
    CP_WAIT(1);
    __syncthreads();
    mma_pass(acc, sb, S_W_HI1, S_W_LO1, m0, n0, lane);
    __syncthreads();
    // ---- epilogue 1 -> P ; W3 -> stage1 ----
    epilogue(acc, smem, sB1, m0, n0, lane);
    cp_issue32k(sb + S_W_HI1, g_w3_hi[dom], tid);
    cp_issue32k(sb + S_W_LO1, g_w3_lo[dom], tid);
    CP_COMMIT();
    CP_WAIT(1);
    __syncthreads();
    mma_pass(acc, sb, S_W_HI0, S_W_LO0, m0, n0, lane);
    __syncthreads();
    // ---- epilogue 2 -> P ----
    epilogue(acc, smem, sB2, m0, n0, lane);
    CP_WAIT(0);
    __syncthreads();
    mma_pass(acc, sb, S_W_HI1, S_W_LO1, m0, n0, lane);
    __syncthreads();

    // ---- head: p = sum_n silu(z3 + b3[n]) * W4[n] ----
    {
        const int lr = lane >> 2, lc = (lane & 3) * 2;
        float hp[2][2] = {{0.0f, 0.0f}, {0.0f, 0.0f}};
#pragma unroll
        for (int t2 = 0; t2 < 2; t2++)
#pragma unroll
            for (int u = 0; u < 8; u++) {
                int n_ = n0 + u * 8 + lc;
                float w0 = sW4[n_], w1 = sW4[n_ + 1];
                float b0 = sB3[n_], b1v = sB3[n_ + 1];
                hp[t2][0] += silu_f(acc[t2][u][0] + b0) * w0 + silu_f(acc[t2][u][1] + b1v) * w1;
                hp[t2][1] += silu_f(acc[t2][u][2] + b0) * w0 + silu_f(acc[t2][u][3] + b1v) * w1;
            }
#pragma unroll
        for (int off = 1; off <= 2; off <<= 1) {
#pragma unroll
            for (int t2 = 0; t2 < 2; t2++) {
                hp[t2][0] += __shfl_xor_sync(0xFFFFFFFF, hp[t2][0], off);
                hp[t2][1] += __shfl_xor_sync(0xFFFFFFFF, hp[t2][1], off);
            }
        }
        if ((lane & 3) == 0) {
#pragma unroll
            for (int t2 = 0; t2 < 2; t2++) {
                sPart[nw * TILE_M + m0 + t2 * 16 + lr]     = hp[t2][0];
                sPart[nw * TILE_M + m0 + t2 * 16 + lr + 8] = hp[t2][1];
            }
        }
    }
    __syncthreads();
    if (tid < nm)
        out[sIdx[tid]] = sPart[tid] + sPart[TILE_M + tid] + b4[dom];
}

// ---------------- launch ----------------
extern "C" void kernel_launch(void* const* d_in, const int* in_sizes, int n_in,
                              void* d_out, int out_size) {
    const float* x  = (const float*)d_in[0];
    const float* t  = (const float*)d_in[1];
    const float* Bf = (const float*)d_in[2];
    const float* W1 = (const float*)d_in[3];
    const float* b1 = (const float*)d_in[4];
    const float* W2 = (const float*)d_in[5];
    const float* b2 = (const float*)d_in[6];
    const float* W3 = (const float*)d_in[7];
    const float* b3 = (const float*)d_in[8];
    const float* W4 = (const float*)d_in[9];
    const float* b4 = (const float*)d_in[10];
    float* out = (float*)d_out;
    const int n = in_sizes[0];
    (void)n_in; (void)out_size;

    cudaFuncSetAttribute(xpinn_mma_kernel,
                         cudaFuncAttributeMaxDynamicSharedMemorySize, SMEM_TOTAL);

    zero_counts_kernel<<<1, 32>>>();
    bucket_kernel<<<(n + 255) / 256, 256>>>(x, n);
    {
        const int total = DNUM * 2 * HDIM * HDIM + 2 * DNUM * HDIM * HDIM;
        prep_weights_kernel<<<(total + 255) / 256, 256>>>(W1, W2, W3);
    }
    dim3 grid((n + TILE_M - 1) / TILE_M, DNUM);
    xpinn_mma_kernel<<<grid, NT, SMEM_TOTAL>>>(x, t, Bf, b1, b2, b3, W4, b4, out);
}

// round 5
// speedup vs baseline: 2.2322x; 1.0862x over previous
#include <cuda_runtime.h>
#include <cuda_fp16.h>
#include <math.h>
#include <stdint.h>

#define DNUM   4
#define N_MAX  262144
#define FDIM   100
#define HDIM   128
#define TILE_M 128
#define NT     512
#define TWO_PI_F 6.2831853071795864769f

// ---------------- device scratch (allocation-free) ----------------
__device__ int g_counts[DNUM];
__device__ int g_idx[DNUM * N_MAX];
// Pre-split (f16 hi/lo), transposed [n][k], XOR-swizzled weight images, 32KB each.
__device__ __align__(16) uint8_t g_w1_hi[DNUM][2][32768];
__device__ __align__(16) uint8_t g_w1_lo[DNUM][2][32768];
__device__ __align__(16) uint8_t g_w2_hi[DNUM][32768];
__device__ __align__(16) uint8_t g_w2_lo[DNUM][32768];
__device__ __align__(16) uint8_t g_w3_hi[DNUM][32768];
__device__ __align__(16) uint8_t g_w3_lo[DNUM][32768];

// swizzled byte offset inside a [128 rows][128 cols-f16] image (256B rows)
__device__ __host__ __forceinline__ int sw_off(int row, int col) {
    return row * 256 + ((((col >> 3) ^ (row & 7)) << 4)) + ((col & 7) << 1);
}

// ---------------- prep kernels ----------------
__global__ void zero_counts_kernel() {
    if (threadIdx.x < DNUM) g_counts[threadIdx.x] = 0;
}
__global__ void bucket_kernel(const float* __restrict__ x, int n) {
    int i = blockIdx.x * blockDim.x + threadIdx.x;
    if (i >= n) return;
    float xv = x[i];
    int d = (xv < -0.5f) ? 0 : (xv < 0.0f) ? 1 : (xv < 0.5f) ? 2 : 3;
    int pos = atomicAdd(&g_counts[d], 1);
    g_idx[d * N_MAX + pos] = i;
}

// W1 col j (0..255): f=j>>1, s=j&1 -> W1 row f+100s (f>=100 pad 0). W2/W3 direct.
__global__ void prep_weights_kernel(const float* __restrict__ W1,
                                    const float* __restrict__ W2,
                                    const float* __restrict__ W3) {
    const int T1 = DNUM * 2 * HDIM * HDIM;
    const int T2 = DNUM * HDIM * HDIM;
    int idx = blockIdx.x * blockDim.x + threadIdx.x;
    float w; uint8_t *hiA, *loA; int off;
    if (idx < T1) {
        int d = idx / (2 * HDIM * HDIM), r = idx % (2 * HDIM * HDIM);
        int c = r / (HDIM * HDIM), r2 = r % (HDIM * HDIM);
        int k = r2 / HDIM, n = r2 % HDIM;
        int j = c * 128 + k, f = j >> 1, s = j & 1;
        w = (f < FDIM) ? W1[((size_t)d * 2 * FDIM + (f + FDIM * s)) * HDIM + n] : 0.0f;
        off = sw_off(n, k); hiA = g_w1_hi[d][c]; loA = g_w1_lo[d][c];
    } else if (idx < T1 + T2) {
        int r0 = idx - T1;
        int d = r0 / (HDIM * HDIM), r2 = r0 % (HDIM * HDIM);
        int k = r2 / HDIM, n = r2 % HDIM;
        w = W2[((size_t)d * HDIM + k) * HDIM + n];
        off = sw_off(n, k); hiA = g_w2_hi[d]; loA = g_w2_lo[d];
    } else if (idx < T1 + 2 * T2) {
        int r0 = idx - T1 - T2;
        int d = r0 / (HDIM * HDIM), r2 = r0 % (HDIM * HDIM);
        int k = r2 / HDIM, n = r2 % HDIM;
        w = W3[((size_t)d * HDIM + k) * HDIM + n];
        off = sw_off(n, k); hiA = g_w3_hi[d]; loA = g_w3_lo[d];
    } else return;
    __half hi = __float2half_rn(w);
    __half lo = __float2half_rn(w - __half2float(hi));
    *(__half*)(hiA + off) = hi;
    *(__half*)(loA + off) = lo;
}

// ---------------- asm helpers ----------------
__device__ __forceinline__ uint32_t smem_u32(const void* p) {
    uint32_t a;
    asm("{ .reg .u64 t; cvta.to.shared.u64 t, %1; cvt.u32.u64 %0, t; }" : "=r"(a) : "l"(p));
    return a;
}
__device__ __forceinline__ void ldsm_x4(uint32_t* r, uint32_t addr) {
    asm volatile("ldmatrix.sync.aligned.m8n8.x4.shared.b16 {%0,%1,%2,%3}, [%4];"
        : "=r"(r[0]), "=r"(r[1]), "=r"(r[2]), "=r"(r[3]) : "r"(addr));
}
__device__ __forceinline__ void mma16816(float* d, const uint32_t* a, uint32_t b0, uint32_t b1) {
    asm volatile("mma.sync.aligned.m16n8k16.row.col.f32.f16.f16.f32 "
        "{%0,%1,%2,%3}, {%4,%5,%6,%7}, {%8,%9}, {%0,%1,%2,%3};"
        : "+f"(d[0]), "+f"(d[1]), "+f"(d[2]), "+f"(d[3])
        : "r"(a[0]), "r"(a[1]), "r"(a[2]), "r"(a[3]), "r"(b0), "r"(b1));
}
#define CP_COMMIT() asm volatile("cp.async.commit_group;" ::: "memory")
#define CP_WAIT(n)  asm volatile("cp.async.wait_group %0;" :: "n"(n) : "memory")
__device__ __forceinline__ void cp_issue32k(uint32_t smem_dst, const uint8_t* gsrc, int tid) {
#pragma unroll
    for (int i = 0; i < 4; i++) {
        int off = (tid + i * NT) * 16;
        asm volatile("cp.async.cg.shared.global [%0], [%1], 16;"
            :: "r"(smem_dst + off), "l"(gsrc + off) : "memory");
    }
}

// ---------------- SMEM layout (bytes) ----------------
#define S_P_HI   0
#define S_P_LO   32768
#define S_W_HI0  65536
#define S_W_LO0  98304
#define S_W_HI1  131072
#define S_W_LO1  163840
#define S_MISC   196608
#define MS_BX    0        // 128 f32
#define MS_BT    512
#define MS_B1    1024
#define MS_B2    1536
#define MS_B3    2048
#define MS_W4    2560
#define MS_X     3072
#define MS_T     3584
#define MS_IDX   4096
#define MS_PART  4608     // 4 x 128 f32
#define SMEM_TOTAL (S_MISC + 4608 + 2048)

__device__ __forceinline__ float silu_f(float v) { return v / (1.0f + __expf(-v)); }
__device__ __forceinline__ uint32_t pack2(float a, float b) {
    __half2 h = __halves2half2(__float2half_rn(a), __float2half_rn(b));
    return *(uint32_t*)&h;
}
__device__ __forceinline__ uint32_t pack2lo(float a, float b) {
    float ar = a - __half2float(__float2half_rn(a));
    float br = b - __half2float(__float2half_rn(b));
    return pack2(ar, br);
}

// One K=128 MMA pass: acc += A(P) * W(stage).  Warp tile: 32(M) x 32(N).
__device__ __forceinline__ void mma_pass(float acc[2][4][4], uint32_t base,
                                         uint32_t wHi, uint32_t wLo,
                                         int m0, int n0, int lane) {
    const int rowl = ((lane >> 3) & 1) * 8 + (lane & 7);  // A and B share this pattern
    const int k8   = (lane >> 4) & 1;
    const int l7   = lane & 7;
#pragma unroll
    for (int ks = 0; ks < 8; ks++) {
        const int swz = ((ks * 2 + k8) ^ l7) << 4;
        uint32_t aH[2][4], aL[2][4];
#pragma unroll
        for (int t = 0; t < 2; t++) {
            uint32_t rb = (uint32_t)(m0 + t * 16 + rowl) * 256 + swz;
            ldsm_x4(aH[t], base + S_P_HI + rb);
            ldsm_x4(aL[t], base + S_P_LO + rb);
        }
        // B: two 16n x 16k ldsm_x4 per hi/lo; regs {r0,r2} = n-lo tile, {r1,r3} = n-hi tile
        uint32_t bH[2][4], bL[2][4];
#pragma unroll
        for (int v = 0; v < 2; v++) {
            uint32_t rb = (uint32_t)(n0 + v * 16 + rowl) * 256 + swz;
            ldsm_x4(bH[v], base + wHi + rb);
            ldsm_x4(bL[v], base + wLo + rb);
        }
#pragma unroll
        for (int v = 0; v < 2; v++) {
#pragma unroll
            for (int h = 0; h < 2; h++) {
                const int u = v * 2 + h;
#pragma unroll
                for (int t = 0; t < 2; t++) {
                    mma16816(acc[t][u], aH[t], bH[v][h], bH[v][h + 2]);
                    mma16816(acc[t][u], aL[t], bH[v][h], bH[v][h + 2]);
                    mma16816(acc[t][u], aH[t], bL[v][h], bL[v][h + 2]);
                }
            }
        }
    }
}

// bias+SiLU, split to f16 hi/lo, store in place into P; zero acc
__device__ __forceinline__ void epilogue(float acc[2][4][4], char* smem,
                                         const float* bias, int m0, int n0, int lane) {
    const int lr = lane >> 2, lc = (lane & 3) * 2;
#pragma unroll
    for (int t = 0; t < 2; t++)
#pragma unroll
        for (int u = 0; u < 4; u++) {
            int n_ = n0 + u * 8 + lc;
            float b0 = bias[n_], b1v = bias[n_ + 1];
            float v0 = silu_f(acc[t][u][0] + b0);
            float v1 = silu_f(acc[t][u][1] + b1v);
            float v2 = silu_f(acc[t][u][2] + b0);
            float v3 = silu_f(acc[t][u][3] + b1v);
            acc[t][u][0] = acc[t][u][1] = acc[t][u][2] = acc[t][u][3] = 0.0f;
            int mA = m0 + t * 16 + lr;
            int chunk = (n_ >> 3) ^ (lr & 7);
            uint32_t addrA = (uint32_t)mA * 256 + (chunk << 4) + lc * 2;
            *(uint32_t*)(smem + S_P_HI + addrA) = pack2(v0, v1);
            *(uint32_t*)(smem + S_P_LO + addrA) = pack2lo(v0, v1);
            int chunkB = (n_ >> 3) ^ ((lr + 8) & 7);
            uint32_t addrB = (uint32_t)(mA + 8) * 256 + (chunkB << 4) + lc * 2;
            *(uint32_t*)(smem + S_P_HI + addrB) = pack2(v2, v3);
            *(uint32_t*)(smem + S_P_LO + addrB) = pack2lo(v2, v3);
        }
}

// Fourier features for one K=128 chunk into P (hi/lo); 512 threads
__device__ __forceinline__ void gen_feats(char* smem, const float* sBx, const float* sBt,
                                          const float* sX, const float* sT,
                                          int chunk, int tid) {
    const int m = tid >> 2, q = tid & 3;
    const float xv = sX[m], tv = sT[m];
    const int fbase = chunk * 64 + q * 16;
#pragma unroll
    for (int g = 0; g < 4; g++) {
        uint32_t hi4[4], lo4[4];
#pragma unroll
        for (int i = 0; i < 4; i++) {
            int f = fbase + g * 4 + i;
            float s = 0.0f, c = 0.0f;
            if (f < FDIM) {
                float pr = TWO_PI_F * (xv * sBx[f] + tv * sBt[f]);
                __sincosf(pr, &s, &c);
            }
            hi4[i] = pack2(s, c);
            lo4[i] = pack2lo(s, c);
        }
        int c0 = q * 32 + g * 8;
        uint32_t addr = (uint32_t)m * 256 + ((((c0 >> 3) ^ (m & 7)) << 4));
        *(uint4*)(smem + S_P_HI + addr) = make_uint4(hi4[0], hi4[1], hi4[2], hi4[3]);
        *(uint4*)(smem + S_P_LO + addr) = make_uint4(lo4[0], lo4[1], lo4[2], lo4[3]);
    }
}

__global__ void __launch_bounds__(NT, 1) xpinn_mma_kernel(
    const float* __restrict__ x, const float* __restrict__ t,
    const float* __restrict__ Bf,
    const float* __restrict__ b1, const float* __restrict__ b2,
    const float* __restrict__ b3,
    const float* __restrict__ W4, const float* __restrict__ b4,
    float* __restrict__ out) {
    const int dom = blockIdx.y;
    const int base_pt = blockIdx.x * TILE_M;
    const int cnt = g_counts[dom];
    if (base_pt >= cnt) return;

    extern __shared__ __align__(16) char smem[];
    const uint32_t sb = smem_u32(smem);
    const int tid = threadIdx.x;
    const int wid = tid >> 5, lane = tid & 31;
    const int m0 = (wid >> 2) * 32, n0 = (wid & 3) * 32, wn = wid & 3;
    const int nm = (cnt - base_pt < TILE_M) ? (cnt - base_pt) : TILE_M;

    float* sBx = (float*)(smem + S_MISC + MS_BX);
    float* sBt = (float*)(smem + S_MISC + MS_BT);
    float* sB1 = (float*)(smem + S_MISC + MS_B1);
    float* sB2 = (float*)(smem + S_MISC + MS_B2);
    float* sB3 = (float*)(smem + S_MISC + MS_B3);
    float* sW4 = (float*)(smem + S_MISC + MS_W4);
    float* sX  = (float*)(smem + S_MISC + MS_X);
    float* sT  = (float*)(smem + S_MISC + MS_T);
    int*   sIdx = (int*)(smem + S_MISC + MS_IDX);
    float* sPart = (float*)(smem + S_MISC + MS_PART);

    // Prefetch W1 both chunks
    cp_issue32k(sb + S_W_HI0, g_w1_hi[dom][0], tid);
    cp_issue32k(sb + S_W_LO0, g_w1_lo[dom][0], tid);
    CP_COMMIT();
    cp_issue32k(sb + S_W_HI1, g_w1_hi[dom][1], tid);
    cp_issue32k(sb + S_W_LO1, g_w1_lo[dom][1], tid);
    CP_COMMIT();

    if (tid < TILE_M) {
        if (tid < nm) {
            int i = g_idx[dom * N_MAX + base_pt + tid];
            sIdx[tid] = i; sX[tid] = x[i]; sT[tid] = t[i];
        } else { sIdx[tid] = -1; sX[tid] = 0.0f; sT[tid] = 0.0f; }
        sBx[tid] = (tid < FDIM) ? Bf[(dom * FDIM + tid) * 2]     : 0.0f;
        sBt[tid] = (tid < FDIM) ? Bf[(dom * FDIM + tid) * 2 + 1] : 0.0f;
        sB1[tid] = b1[dom * HDIM + tid];
        sB2[tid] = b2[dom * HDIM + tid];
        sB3[tid] = b3[dom * HDIM + tid];
        sW4[tid] = W4[dom * HDIM + tid];
    }
    __syncthreads();

    float acc[2][4][4];
#pragma unroll
    for (int t2 = 0; t2 < 2; t2++)
#pragma unroll
        for (int u = 0; u < 4; u++)
#pragma unroll
            for (int r = 0; r < 4; r++) acc[t2][u][r] = 0.0f;

    // ---- layer 1, K chunk 0 ----
    gen_feats(smem, sBx, sBt, sX, sT, 0, tid);
    CP_WAIT(1);
    __syncthreads();
    mma_pass(acc, sb, S_W_HI0, S_W_LO0, m0, n0, lane);
    __syncthreads();
    // ---- layer 1, K chunk 1 (feats in place; W2 -> stage0) ----
    gen_feats(smem, sBx, sBt, sX, sT, 1, tid);
    cp_issue32k(sb + S_W_HI0, g_w2_hi[dom], tid);
    cp_issue32k(sb + S_W_LO0, g_w2_lo[dom], tid);
    CP_COMMIT();
    CP_WAIT(1);
    __syncthreads();
    mma_pass(acc, sb, S_W_HI1, S_W_LO1, m0, n0, lane);
    __syncthreads();
    // ---- epilogue 1 -> P ; W3 -> stage1 ----
    epilogue(acc, smem, sB1, m0, n0, lane);
    cp_issue32k(sb + S_W_HI1, g_w3_hi[dom], tid);
    cp_issue32k(sb + S_W_LO1, g_w3_lo[dom], tid);
    CP_COMMIT();
    CP_WAIT(1);
    __syncthreads();
    mma_pass(acc, sb, S_W_HI0, S_W_LO0, m0, n0, lane);
    __syncthreads();
    // ---- epilogue 2 -> P ----
    epilogue(acc, smem, sB2, m0, n0, lane);
    CP_WAIT(0);
    __syncthreads();
    mma_pass(acc, sb, S_W_HI1, S_W_LO1, m0, n0, lane);
    __syncthreads();

    // ---- head: p = sum_n silu(z3 + b3[n]) * W4[n] ----
    {
        const int lr = lane >> 2, lc = (lane & 3) * 2;
        float hp[2][2] = {{0.0f, 0.0f}, {0.0f, 0.0f}};
#pragma unroll
        for (int t2 = 0; t2 < 2; t2++)
#pragma unroll
            for (int u = 0; u < 4; u++) {
                int n_ = n0 + u * 8 + lc;
                float w0 = sW4[n_], w1 = sW4[n_ + 1];
                float b0 = sB3[n_], b1v = sB3[n_ + 1];
                hp[t2][0] += silu_f(acc[t2][u][0] + b0) * w0 + silu_f(acc[t2][u][1] + b1v) * w1;
                hp[t2][1] += silu_f(acc[t2][u][2] + b0) * w0 + silu_f(acc[t2][u][3] + b1v) * w1;
            }
#pragma unroll
        for (int off = 1; off <= 2; off <<= 1) {
#pragma unroll
            for (int t2 = 0; t2 < 2; t2++) {
                hp[t2][0] += __shfl_xor_sync(0xFFFFFFFF, hp[t2][0], off);
                hp[t2][1] += __shfl_xor_sync(0xFFFFFFFF, hp[t2][1], off);
            }
        }
        if ((lane & 3) == 0) {
#pragma unroll
            for (int t2 = 0; t2 < 2; t2++) {
                sPart[wn * TILE_M + m0 + t2 * 16 + lr]     = hp[t2][0];
                sPart[wn * TILE_M + m0 + t2 * 16 + lr + 8] = hp[t2][1];
            }
        }
    }
    __syncthreads();
    if (tid < nm)
        out[sIdx[tid]] = sPart[tid] + sPart[TILE_M + tid]
                       + sPart[2 * TILE_M + tid] + sPart[3 * TILE_M + tid] + b4[dom];
}

// ---------------- launch ----------------
extern "C" void kernel_launch(void* const* d_in, const int* in_sizes, int n_in,
                              void* d_out, int out_size) {
    const float* x  = (const float*)d_in[0];
    const float* t  = (const float*)d_in[1];
    const float* Bf = (const float*)d_in[2];
    const float* W1 = (const float*)d_in[3];
    const float* b1 = (const float*)d_in[4];
    const float* W2 = (const float*)d_in[5];
    const float* b2 = (const float*)d_in[6];
    const float* W3 = (const float*)d_in[7];
    const float* b3 = (const float*)d_in[8];
    const float* W4 = (const float*)d_in[9];
    const float* b4 = (const float*)d_in[10];
    float* out = (float*)d_out;
    const int n = in_sizes[0];
    (void)n_in; (void)out_size;

    cudaFuncSetAttribute(xpinn_mma_kernel,
                         cudaFuncAttributeMaxDynamicSharedMemorySize, SMEM_TOTAL);

    zero_counts_kernel<<<1, 32>>>();
    bucket_kernel<<<(n + 255) / 256, 256>>>(x, n);
    {
        const int total = DNUM * 2 * HDIM * HDIM + 2 * DNUM * HDIM * HDIM;
        prep_weights_kernel<<<(total + 255) / 256, 256>>>(W1, W2, W3);
    }
    dim3 grid((n + TILE_M - 1) / TILE_M, DNUM);
    xpinn_mma_kernel<<<grid, NT, SMEM_TOTAL>>>(x, t, Bf, b1, b2, b3, W4, b4, out);
}

// round 6
// speedup vs baseline: 2.6809x; 1.2010x over previous
#include <cuda_runtime.h>
#include <cuda_fp16.h>
#include <math.h>
#include <stdint.h>

#define DNUM   4
#define N_MAX  262144
#define FDIM   100
#define HDIM   128
#define TILE_M 128
#define NT     512
#define TWO_PI_F 6.2831853071795864769f

// ---------------- device scratch (allocation-free) ----------------
__device__ int g_counts[DNUM];
__device__ int g_idx[DNUM * N_MAX];
// f16 weights, transposed [n][k], XOR-swizzled images, 32KB each.
__device__ __align__(16) uint8_t g_w1_hi[DNUM][2][32768];
__device__ __align__(16) uint8_t g_w2_hi[DNUM][32768];
__device__ __align__(16) uint8_t g_w3_hi[DNUM][32768];

// swizzled byte offset inside a [128 rows][128 cols-f16] image (256B rows)
__device__ __host__ __forceinline__ int sw_off(int row, int col) {
    return row * 256 + ((((col >> 3) ^ (row & 7)) << 4)) + ((col & 7) << 1);
}

// ---------------- prep kernels ----------------
__global__ void zero_counts_kernel() {
    if (threadIdx.x < DNUM) g_counts[threadIdx.x] = 0;
}
__global__ void bucket_kernel(const float* __restrict__ x, int n) {
    int i = blockIdx.x * blockDim.x + threadIdx.x;
    if (i >= n) return;
    float xv = x[i];
    int d = (xv < -0.5f) ? 0 : (xv < 0.0f) ? 1 : (xv < 0.5f) ? 2 : 3;
    int pos = atomicAdd(&g_counts[d], 1);
    g_idx[d * N_MAX + pos] = i;
}

// W1 col j (0..255): f=j>>1, s=j&1 -> W1 row f+100s (f>=100 pad 0). W2/W3 direct.
__global__ void prep_weights_kernel(const float* __restrict__ W1,
                                    const float* __restrict__ W2,
                                    const float* __restrict__ W3) {
    const int T1 = DNUM * 2 * HDIM * HDIM;
    const int T2 = DNUM * HDIM * HDIM;
    int idx = blockIdx.x * blockDim.x + threadIdx.x;
    float w; uint8_t* hiA; int off;
    if (idx < T1) {
        int d = idx / (2 * HDIM * HDIM), r = idx % (2 * HDIM * HDIM);
        int c = r / (HDIM * HDIM), r2 = r % (HDIM * HDIM);
        int k = r2 / HDIM, n = r2 % HDIM;
        int j = c * 128 + k, f = j >> 1, s = j & 1;
        w = (f < FDIM) ? W1[((size_t)d * 2 * FDIM + (f + FDIM * s)) * HDIM + n] : 0.0f;
        off = sw_off(n, k); hiA = g_w1_hi[d][c];
    } else if (idx < T1 + T2) {
        int r0 = idx - T1;
        int d = r0 / (HDIM * HDIM), r2 = r0 % (HDIM * HDIM);
        int k = r2 / HDIM, n = r2 % HDIM;
        w = W2[((size_t)d * HDIM + k) * HDIM + n];
        off = sw_off(n, k); hiA = g_w2_hi[d];
    } else if (idx < T1 + 2 * T2) {
        int r0 = idx - T1 - T2;
        int d = r0 / (HDIM * HDIM), r2 = r0 % (HDIM * HDIM);
        int k = r2 / HDIM, n = r2 % HDIM;
        w = W3[((size_t)d * HDIM + k) * HDIM + n];
        off = sw_off(n, k); hiA = g_w3_hi[d];
    } else return;
    *(__half*)(hiA + off) = __float2half_rn(w);
}

// ---------------- asm helpers ----------------
__device__ __forceinline__ uint32_t smem_u32(const void* p) {
    uint32_t a;
    asm("{ .reg .u64 t; cvta.to.shared.u64 t, %1; cvt.u32.u64 %0, t; }" : "=r"(a) : "l"(p));
    return a;
}
__device__ __forceinline__ void ldsm_x4(uint32_t* r, uint32_t addr) {
    asm volatile("ldmatrix.sync.aligned.m8n8.x4.shared.b16 {%0,%1,%2,%3}, [%4];"
        : "=r"(r[0]), "=r"(r[1]), "=r"(r[2]), "=r"(r[3]) : "r"(addr));
}
__device__ __forceinline__ void mma16816(float* d, const uint32_t* a, uint32_t b0, uint32_t b1) {
    asm volatile("mma.sync.aligned.m16n8k16.row.col.f32.f16.f16.f32 "
        "{%0,%1,%2,%3}, {%4,%5,%6,%7}, {%8,%9}, {%0,%1,%2,%3};"
        : "+f"(d[0]), "+f"(d[1]), "+f"(d[2]), "+f"(d[3])
        : "r"(a[0]), "r"(a[1]), "r"(a[2]), "r"(a[3]), "r"(b0), "r"(b1));
}
#define CP_COMMIT() asm volatile("cp.async.commit_group;" ::: "memory")
#define CP_WAIT(n)  asm volatile("cp.async.wait_group %0;" :: "n"(n) : "memory")
__device__ __forceinline__ void cp_issue32k(uint32_t smem_dst, const uint8_t* gsrc, int tid) {
#pragma unroll
    for (int i = 0; i < 4; i++) {
        int off = (tid + i * NT) * 16;
        asm volatile("cp.async.cg.shared.global [%0], [%1], 16;"
            :: "r"(smem_dst + off), "l"(gsrc + off) : "memory");
    }
}

// ---------------- SMEM layout (bytes) ----------------
#define S_P_HI   0
#define S_P_LO   32768
#define S_W1C0   65536
#define S_W1C1   98304
#define S_W2     131072
#define S_W3     163840
#define S_MISC   196608
#define MS_BX    0        // 128 f32
#define MS_BT    512
#define MS_B1    1024
#define MS_B2    1536
#define MS_B3    2048
#define MS_W4    2560
#define MS_X     3072
#define MS_T     3584
#define MS_IDX   4096
#define MS_PART  4608     // 4 x 128 f32
#define SMEM_TOTAL (S_MISC + 4608 + 2048)

__device__ __forceinline__ float silu_f(float v) { return v / (1.0f + __expf(-v)); }
__device__ __forceinline__ uint32_t pack2(float a, float b) {
    __half2 h = __halves2half2(__float2half_rn(a), __float2half_rn(b));
    return *(uint32_t*)&h;
}
__device__ __forceinline__ uint32_t pack2lo(float a, float b) {
    float ar = a - __half2float(__float2half_rn(a));
    float br = b - __half2float(__float2half_rn(b));
    return pack2(ar, br);
}

// One K=128 MMA pass: acc += (Ah+Al) * Wh.  Warp tile: 32(M) x 32(N).
__device__ __forceinline__ void mma_pass(float acc[2][4][4], uint32_t base,
                                         uint32_t wOff, int m0, int n0, int lane) {
    const int rowl = ((lane >> 3) & 1) * 8 + (lane & 7);
    const int k8   = (lane >> 4) & 1;
    const int l7   = lane & 7;
    const uint32_t aBase0 = base + S_P_HI + (uint32_t)(m0 + rowl) * 256;
    const uint32_t aBase1 = base + S_P_HI + (uint32_t)(m0 + 16 + rowl) * 256;
    const uint32_t lOfs   = S_P_LO - S_P_HI;
    const uint32_t bBase0 = base + wOff + (uint32_t)(n0 + rowl) * 256;
    const uint32_t bBase1 = base + wOff + (uint32_t)(n0 + 16 + rowl) * 256;
#pragma unroll
    for (int ks = 0; ks < 8; ks++) {
        const uint32_t swz = (uint32_t)(((ks * 2 + k8) ^ l7) << 4);
        uint32_t aH[2][4], aL[2][4], bH[2][4];
        ldsm_x4(aH[0], aBase0 + swz);
        ldsm_x4(aH[1], aBase1 + swz);
        ldsm_x4(aL[0], aBase0 + lOfs + swz);
        ldsm_x4(aL[1], aBase1 + lOfs + swz);
        ldsm_x4(bH[0], bBase0 + swz);
        ldsm_x4(bH[1], bBase1 + swz);
#pragma unroll
        for (int v = 0; v < 2; v++)
#pragma unroll
            for (int h = 0; h < 2; h++) {
                const int u = v * 2 + h;
                mma16816(acc[0][u], aH[0], bH[v][h], bH[v][h + 2]);
                mma16816(acc[1][u], aH[1], bH[v][h], bH[v][h + 2]);
                mma16816(acc[0][u], aL[0], bH[v][h], bH[v][h + 2]);
                mma16816(acc[1][u], aL[1], bH[v][h], bH[v][h + 2]);
            }
    }
}

// bias+SiLU, split to f16 hi/lo, store in place into P; zero acc
__device__ __forceinline__ void epilogue(float acc[2][4][4], char* smem,
                                         const float* bias, int m0, int n0, int lane) {
    const int lr = lane >> 2, lc = (lane & 3) * 2;
#pragma unroll
    for (int t = 0; t < 2; t++)
#pragma unroll
        for (int u = 0; u < 4; u++) {
            int n_ = n0 + u * 8 + lc;
            float b0 = bias[n_], b1v = bias[n_ + 1];
            float v0 = silu_f(acc[t][u][0] + b0);
            float v1 = silu_f(acc[t][u][1] + b1v);
            float v2 = silu_f(acc[t][u][2] + b0);
            float v3 = silu_f(acc[t][u][3] + b1v);
            acc[t][u][0] = acc[t][u][1] = acc[t][u][2] = acc[t][u][3] = 0.0f;
            int mA = m0 + t * 16 + lr;
            int chunk = (n_ >> 3) ^ (lr & 7);
            uint32_t addrA = (uint32_t)mA * 256 + (chunk << 4) + lc * 2;
            *(uint32_t*)(smem + S_P_HI + addrA) = pack2(v0, v1);
            *(uint32_t*)(smem + S_P_LO + addrA) = pack2lo(v0, v1);
            int chunkB = (n_ >> 3) ^ ((lr + 8) & 7);
            uint32_t addrB = (uint32_t)(mA + 8) * 256 + (chunkB << 4) + lc * 2;
            *(uint32_t*)(smem + S_P_HI + addrB) = pack2(v2, v3);
            *(uint32_t*)(smem + S_P_LO + addrB) = pack2lo(v2, v3);
        }
}

// Fourier features for one K=128 chunk into P (hi/lo); 512 threads
__device__ __forceinline__ void gen_feats(char* smem, const float* sBx, const float* sBt,
                                          const float* sX, const float* sT,
                                          int chunk, int tid) {
    const int m = tid >> 2, q = tid & 3;
    const float xv = sX[m], tv = sT[m];
    const int fbase = chunk * 64 + q * 16;
#pragma unroll
    for (int g = 0; g < 4; g++) {
        uint32_t hi4[4], lo4[4];
#pragma unroll
        for (int i = 0; i < 4; i++) {
            int f = fbase + g * 4 + i;
            float s = 0.0f, c = 0.0f;
            if (f < FDIM) {
                float pr = TWO_PI_F * (xv * sBx[f] + tv * sBt[f]);
                __sincosf(pr, &s, &c);
            }
            hi4[i] = pack2(s, c);
            lo4[i] = pack2lo(s, c);
        }
        int c0 = q * 32 + g * 8;
        uint32_t addr = (uint32_t)m * 256 + ((((c0 >> 3) ^ (m & 7)) << 4));
        *(uint4*)(smem + S_P_HI + addr) = make_uint4(hi4[0], hi4[1], hi4[2], hi4[3]);
        *(uint4*)(smem + S_P_LO + addr) = make_uint4(lo4[0], lo4[1], lo4[2], lo4[3]);
    }
}

__global__ void __launch_bounds__(NT, 1) xpinn_mma_kernel(
    const float* __restrict__ x, const float* __restrict__ t,
    const float* __restrict__ Bf,
    const float* __restrict__ b1, const float* __restrict__ b2,
    const float* __restrict__ b3,
    const float* __restrict__ W4, const float* __restrict__ b4,
    float* __restrict__ out) {
    const int dom = blockIdx.y;
    const int base_pt = blockIdx.x * TILE_M;
    const int cnt = g_counts[dom];
    if (base_pt >= cnt) return;

    extern __shared__ __align__(16) char smem[];
    const uint32_t sb = smem_u32(smem);
    const int tid = threadIdx.x;
    const int wid = tid >> 5, lane = tid & 31;
    const int m0 = (wid >> 2) * 32, n0 = (wid & 3) * 32, wn = wid & 3;
    const int nm = (cnt - base_pt < TILE_M) ? (cnt - base_pt) : TILE_M;

    float* sBx = (float*)(smem + S_MISC + MS_BX);
    float* sBt = (float*)(smem + S_MISC + MS_BT);
    float* sB1 = (float*)(smem + S_MISC + MS_B1);
    float* sB2 = (float*)(smem + S_MISC + MS_B2);
    float* sB3 = (float*)(smem + S_MISC + MS_B3);
    float* sW4 = (float*)(smem + S_MISC + MS_W4);
    float* sX  = (float*)(smem + S_MISC + MS_X);
    float* sT  = (float*)(smem + S_MISC + MS_T);
    int*   sIdx = (int*)(smem + S_MISC + MS_IDX);
    float* sPart = (float*)(smem + S_MISC + MS_PART);

    // Prefetch ALL weights up front: 4 cp.async groups.
    cp_issue32k(sb + S_W1C0, g_w1_hi[dom][0], tid); CP_COMMIT();
    cp_issue32k(sb + S_W1C1, g_w1_hi[dom][1], tid); CP_COMMIT();
    cp_issue32k(sb + S_W2,   g_w2_hi[dom],    tid); CP_COMMIT();
    cp_issue32k(sb + S_W3,   g_w3_hi[dom],    tid); CP_COMMIT();

    if (tid < TILE_M) {
        if (tid < nm) {
            int i = g_idx[dom * N_MAX + base_pt + tid];
            sIdx[tid] = i; sX[tid] = x[i]; sT[tid] = t[i];
        } else { sIdx[tid] = -1; sX[tid] = 0.0f; sT[tid] = 0.0f; }
        sBx[tid] = (tid < FDIM) ? Bf[(dom * FDIM + tid) * 2]     : 0.0f;
        sBt[tid] = (tid < FDIM) ? Bf[(dom * FDIM + tid) * 2 + 1] : 0.0f;
        sB1[tid] = b1[dom * HDIM + tid];
        sB2[tid] = b2[dom * HDIM + tid];
        sB3[tid] = b3[dom * HDIM + tid];
        sW4[tid] = W4[dom * HDIM + tid];
    }
    __syncthreads();

    float acc[2][4][4];
#pragma unroll
    for (int t2 = 0; t2 < 2; t2++)
#pragma unroll
        for (int u = 0; u < 4; u++)
#pragma unroll
            for (int r = 0; r < 4; r++) acc[t2][u][r] = 0.0f;

    // ---- layer 1, K chunk 0 ----
    gen_feats(smem, sBx, sBt, sX, sT, 0, tid);
    CP_WAIT(3);
    __syncthreads();
    mma_pass(acc, sb, S_W1C0, m0, n0, lane);
    __syncthreads();
    // ---- layer 1, K chunk 1 (feats regenerated in place) ----
    gen_feats(smem, sBx, sBt, sX, sT, 1, tid);
    CP_WAIT(2);
    __syncthreads();
    mma_pass(acc, sb, S_W1C1, m0, n0, lane);
    __syncthreads();
    // ---- layer 2 ----
    epilogue(acc, smem, sB1, m0, n0, lane);
    CP_WAIT(1);
    __syncthreads();
    mma_pass(acc, sb, S_W2, m0, n0, lane);
    __syncthreads();
    // ---- layer 3 ----
    epilogue(acc, smem, sB2, m0, n0, lane);
    CP_WAIT(0);
    __syncthreads();
    mma_pass(acc, sb, S_W3, m0, n0, lane);
    __syncthreads();

    // ---- head: p = sum_n silu(z3 + b3[n]) * W4[n] ----
    {
        const int lr = lane >> 2, lc = (lane & 3) * 2;
        float hp[2][2] = {{0.0f, 0.0f}, {0.0f, 0.0f}};
#pragma unroll
        for (int t2 = 0; t2 < 2; t2++)
#pragma unroll
            for (int u = 0; u < 4; u++) {
                int n_ = n0 + u * 8 + lc;
                float w0 = sW4[n_], w1 = sW4[n_ + 1];
                float b0 = sB3[n_], b1v = sB3[n_ + 1];
                hp[t2][0] += silu_f(acc[t2][u][0] + b0) * w0 + silu_f(acc[t2][u][1] + b1v) * w1;
                hp[t2][1] += silu_f(acc[t2][u][2] + b0) * w0 + silu_f(acc[t2][u][3] + b1v) * w1;
            }
#pragma unroll
        for (int off = 1; off <= 2; off <<= 1) {
#pragma unroll
            for (int t2 = 0; t2 < 2; t2++) {
                hp[t2][0] += __shfl_xor_sync(0xFFFFFFFF, hp[t2][0], off);
                hp[t2][1] += __shfl_xor_sync(0xFFFFFFFF, hp[t2][1], off);
            }
        }
        if ((lane & 3) == 0) {
#pragma unroll
            for (int t2 = 0; t2 < 2; t2++) {
                sPart[wn * TILE_M + m0 + t2 * 16 + lr]     = hp[t2][0];
                sPart[wn * TILE_M + m0 + t2 * 16 + lr + 8] = hp[t2][1];
            }
        }
    }
    __syncthreads();
    if (tid < nm)
        out[sIdx[tid]] = sPart[tid] + sPart[TILE_M + tid]
                       + sPart[2 * TILE_M + tid] + sPart[3 * TILE_M + tid] + b4[dom];
}

// ---------------- launch ----------------
extern "C" void kernel_launch(void* const* d_in, const int* in_sizes, int n_in,
                              void* d_out, int out_size) {
    const float* x  = (const float*)d_in[0];
    const float* t  = (const float*)d_in[1];
    const float* Bf = (const float*)d_in[2];
    const float* W1 = (const float*)d_in[3];
    const float* b1 = (const float*)d_in[4];
    const float* W2 = (const float*)d_in[5];
    const float* b2 = (const float*)d_in[6];
    const float* W3 = (const float*)d_in[7];
    const float* b3 = (const float*)d_in[8];
    const float* W4 = (const float*)d_in[9];
    const float* b4 = (const float*)d_in[10];
    float* out = (float*)d_out;
    const int n = in_sizes[0];
    (void)n_in; (void)out_size;

    cudaFuncSetAttribute(xpinn_mma_kernel,
                         cudaFuncAttributeMaxDynamicSharedMemorySize, SMEM_TOTAL);

    zero_counts_kernel<<<1, 32>>>();
    bucket_kernel<<<(n + 255) / 256, 256>>>(x, n);
    {
        const int total = DNUM * 2 * HDIM * HDIM + 2 * DNUM * HDIM * HDIM;
        prep_weights_kernel<<<(total + 255) / 256, 256>>>(W1, W2, W3);
    }
    dim3 grid((n + TILE_M - 1) / TILE_M, DNUM);
    xpinn_mma_kernel<<<grid, NT, SMEM_TOTAL>>>(x, t, Bf, b1, b2, b3, W4, b4, out);
}

// round 9
// speedup vs baseline: 3.9221x; 1.4630x over previous
#include <cuda_runtime.h>
#include <cuda_fp16.h>
#include <math.h>
#include <stdint.h>

#define DNUM   4
#define N_MAX  262144
#define FDIM   100
#define HDIM   128
#define TILE_M 128
#define NT     256
#define TWO_PI_F 6.2831853071795864769f

// ---------------- device scratch (allocation-free) ----------------
__device__ int g_counts[DNUM];
__device__ int g_idx[DNUM * N_MAX];
// f16 weights, transposed [n][k], XOR-swizzled images, 32KB each.
__device__ __align__(16) uint8_t g_w1_hi[DNUM][2][32768];
__device__ __align__(16) uint8_t g_w2_hi[DNUM][32768];
__device__ __align__(16) uint8_t g_w3_hi[DNUM][32768];

// swizzled byte offset inside a [128 rows][128 cols-f16] image (256B rows)
__device__ __host__ __forceinline__ int sw_off(int row, int col) {
    return row * 256 + ((((col >> 3) ^ (row & 7)) << 4)) + ((col & 7) << 1);
}

// ---------------- prep kernels ----------------
__global__ void zero_counts_kernel() {
    if (threadIdx.x < DNUM) g_counts[threadIdx.x] = 0;
}
__global__ void bucket_kernel(const float* __restrict__ x, int n) {
    int i = blockIdx.x * blockDim.x + threadIdx.x;
    if (i >= n) return;
    float xv = x[i];
    int d = (xv < -0.5f) ? 0 : (xv < 0.0f) ? 1 : (xv < 0.5f) ? 2 : 3;
    int pos = atomicAdd(&g_counts[d], 1);
    g_idx[d * N_MAX + pos] = i;
}

// W1 col j (0..255): f=j>>1, s=j&1 -> W1 row f+100s (f>=100 pad 0). W2/W3 direct.
__global__ void prep_weights_kernel(const float* __restrict__ W1,
                                    const float* __restrict__ W2,
                                    const float* __restrict__ W3) {
    const int T1 = DNUM * 2 * HDIM * HDIM;
    const int T2 = DNUM * HDIM * HDIM;
    int idx = blockIdx.x * blockDim.x + threadIdx.x;
    float w; uint8_t* hiA; int off;
    if (idx < T1) {
        int d = idx / (2 * HDIM * HDIM), r = idx % (2 * HDIM * HDIM);
        int c = r / (HDIM * HDIM), r2 = r % (HDIM * HDIM);
        int k = r2 / HDIM, n = r2 % HDIM;
        int j = c * 128 + k, f = j >> 1, s = j & 1;
        w = (f < FDIM) ? W1[((size_t)d * 2 * FDIM + (f + FDIM * s)) * HDIM + n] : 0.0f;
        off = sw_off(n, k); hiA = g_w1_hi[d][c];
    } else if (idx < T1 + T2) {
        int r0 = idx - T1;
        int d = r0 / (HDIM * HDIM), r2 = r0 % (HDIM * HDIM);
        int k = r2 / HDIM, n = r2 % HDIM;
        w = W2[((size_t)d * HDIM + k) * HDIM + n];
        off = sw_off(n, k); hiA = g_w2_hi[d];
    } else if (idx < T1 + 2 * T2) {
        int r0 = idx - T1 - T2;
        int d = r0 / (HDIM * HDIM), r2 = r0 % (HDIM * HDIM);
        int k = r2 / HDIM, n = r2 % HDIM;
        w = W3[((size_t)d * HDIM + k) * HDIM + n];
        off = sw_off(n, k); hiA = g_w3_hi[d];
    } else return;
    *(__half*)(hiA + off) = __float2half_rn(w);
}

// ---------------- asm helpers ----------------
__device__ __forceinline__ uint32_t smem_u32(const void* p) {
    uint32_t a;
    asm("{ .reg .u64 t; cvta.to.shared.u64 t, %1; cvt.u32.u64 %0, t; }" : "=r"(a) : "l"(p));
    return a;
}
__device__ __forceinline__ void ldsm_x4(uint32_t* r, uint32_t addr) {
    asm volatile("ldmatrix.sync.aligned.m8n8.x4.shared.b16 {%0,%1,%2,%3}, [%4];"
        : "=r"(r[0]), "=r"(r[1]), "=r"(r[2]), "=r"(r[3]) : "r"(addr));
}
__device__ __forceinline__ void mma16816(float* d, const uint32_t* a, uint32_t b0, uint32_t b1) {
    asm volatile("mma.sync.aligned.m16n8k16.row.col.f32.f16.f16.f32 "
        "{%0,%1,%2,%3}, {%4,%5,%6,%7}, {%8,%9}, {%0,%1,%2,%3};"
        : "+f"(d[0]), "+f"(d[1]), "+f"(d[2]), "+f"(d[3])
        : "r"(a[0]), "r"(a[1]), "r"(a[2]), "r"(a[3]), "r"(b0), "r"(b1));
}
#define CP_COMMIT() asm volatile("cp.async.commit_group;" ::: "memory")
#define CP_WAIT(n)  asm volatile("cp.async.wait_group %0;" :: "n"(n) : "memory")
__device__ __forceinline__ void cp_issue32k(uint32_t smem_dst, const uint8_t* gsrc, int tid) {
#pragma unroll
    for (int i = 0; i < 8; i++) {
        int off = (tid + i * NT) * 16;
        asm volatile("cp.async.cg.shared.global [%0], [%1], 16;"
            :: "r"(smem_dst + off), "l"(gsrc + off) : "memory");
    }
}

// ---------------- SMEM layout (bytes) ----------------
#define S_P      0          // activations, 128x128 f16 swizzled, 32KB
#define S_W0     32768      // weight stage 0, 32KB
#define S_W1     65536      // weight stage 1, 32KB
#define S_MISC   98304
#define MS_BX    0          // 128 f32
#define MS_BT    512
#define MS_B1    1024
#define MS_B2    1536
#define MS_B3    2048
#define MS_W4    2560
#define MS_X     3072
#define MS_T     3584
#define MS_IDX   4096
#define MS_PART  4608       // 4 x 128 f32
#define SMEM_TOTAL (S_MISC + 4608 + 2048)

__device__ __forceinline__ float silu_f(float v) { return v / (1.0f + __expf(-v)); }
__device__ __forceinline__ uint32_t pack2(float a, float b) {
    __half2 h = __halves2half2(__float2half_rn(a), __float2half_rn(b));
    return *(uint32_t*)&h;
}

// One K=128 MMA pass: acc += A(P) * W(stage).  Warp tile: 64(M) x 32(N).
__device__ __forceinline__ void mma_pass(float acc[4][4][4], uint32_t base,
                                         uint32_t wOff, int m0, int n0, int lane) {
    const int rowl = ((lane >> 3) & 1) * 8 + (lane & 7);
    const int k8   = (lane >> 4) & 1;
    const int l7   = lane & 7;
    uint32_t aBase[4], bBase[2];
#pragma unroll
    for (int s = 0; s < 4; s++)
        aBase[s] = base + S_P + (uint32_t)(m0 + s * 16 + rowl) * 256;
#pragma unroll
    for (int v = 0; v < 2; v++)
        bBase[v] = base + wOff + (uint32_t)(n0 + v * 16 + rowl) * 256;
#pragma unroll
    for (int ks = 0; ks < 8; ks++) {
        const uint32_t swz = (uint32_t)(((ks * 2 + k8) ^ l7) << 4);
        uint32_t aH[4][4], bH[2][4];
#pragma unroll
        for (int s = 0; s < 4; s++) ldsm_x4(aH[s], aBase[s] + swz);
#pragma unroll
        for (int v = 0; v < 2; v++) ldsm_x4(bH[v], bBase[v] + swz);
#pragma unroll
        for (int v = 0; v < 2; v++)
#pragma unroll
            for (int h = 0; h < 2; h++) {
                const int u = v * 2 + h;
#pragma unroll
                for (int s = 0; s < 4; s++)
                    mma16816(acc[s][u], aH[s], bH[v][h], bH[v][h + 2]);
            }
    }
}

// bias+SiLU, round to f16, store in place into P; zero acc
__device__ __forceinline__ void epilogue(float acc[4][4][4], char* smem,
                                         const float* bias, int m0, int n0, int lane) {
    const int lr = lane >> 2, lc = (lane & 3) * 2;
#pragma unroll
    for (int s = 0; s < 4; s++)
#pragma unroll
        for (int u = 0; u < 4; u++) {
            int n_ = n0 + u * 8 + lc;
            float b0 = bias[n_], b1v = bias[n_ + 1];
            float v0 = silu_f(acc[s][u][0] + b0);
            float v1 = silu_f(acc[s][u][1] + b1v);
            float v2 = silu_f(acc[s][u][2] + b0);
            float v3 = silu_f(acc[s][u][3] + b1v);
            acc[s][u][0] = acc[s][u][1] = acc[s][u][2] = acc[s][u][3] = 0.0f;
            int mA = m0 + s * 16 + lr;
            int chunk = (n_ >> 3) ^ (lr & 7);
            uint32_t addrA = (uint32_t)mA * 256 + (chunk << 4) + lc * 2;
            *(uint32_t*)(smem + S_P + addrA) = pack2(v0, v1);
            int chunkB = (n_ >> 3) ^ ((lr + 8) & 7);
            uint32_t addrB = (uint32_t)(mA + 8) * 256 + (chunkB << 4) + lc * 2;
            *(uint32_t*)(smem + S_P + addrB) = pack2(v2, v3);
        }
}

// Fourier features for one K=128 chunk into P; 256 threads
__device__ __forceinline__ void gen_feats(char* smem, const float* sBx, const float* sBt,
                                          const float* sX, const float* sT,
                                          int chunk, int tid) {
    const int m = tid >> 1, q = tid & 1;
    const float xv = sX[m], tv = sT[m];
    const int fbase = chunk * 64 + q * 32;
#pragma unroll
    for (int g = 0; g < 8; g++) {
        uint32_t hi4[4];
#pragma unroll
        for (int i = 0; i < 4; i++) {
            int f = fbase + g * 4 + i;
            float s = 0.0f, c = 0.0f;
            if (f < FDIM) {
                float pr = TWO_PI_F * (xv * sBx[f] + tv * sBt[f]);
                __sincosf(pr, &s, &c);
            }
            hi4[i] = pack2(s, c);
        }
        int c0 = q * 64 + g * 8;
        uint32_t addr = (uint32_t)m * 256 + ((((c0 >> 3) ^ (m & 7)) << 4));
        *(uint4*)(smem + S_P + addr) = make_uint4(hi4[0], hi4[1], hi4[2], hi4[3]);
    }
}

__global__ void __launch_bounds__(NT, 2) xpinn_mma_kernel(
    const float* __restrict__ x, const float* __restrict__ t,
    const float* __restrict__ Bf,
    const float* __restrict__ b1, const float* __restrict__ b2,
    const float* __restrict__ b3,
    const float* __restrict__ W4, const float* __restrict__ b4,
    float* __restrict__ out) {
    const int dom = blockIdx.y;
    const int base_pt = blockIdx.x * TILE_M;
    const int cnt = g_counts[dom];
    if (base_pt >= cnt) return;

    extern __shared__ __align__(16) char smem[];
    const uint32_t sb = smem_u32(smem);
    const int tid = threadIdx.x;
    const int wid = tid >> 5, lane = tid & 31;
    const int m0 = (wid >> 2) * 64, n0 = (wid & 3) * 32, wn = wid & 3;
    const int nm = (cnt - base_pt < TILE_M) ? (cnt - base_pt) : TILE_M;

    float* sBx = (float*)(smem + S_MISC + MS_BX);
    float* sBt = (float*)(smem + S_MISC + MS_BT);
    float* sB1 = (float*)(smem + S_MISC + MS_B1);
    float* sB2 = (float*)(smem + S_MISC + MS_B2);
    float* sB3 = (float*)(smem + S_MISC + MS_B3);
    float* sW4 = (float*)(smem + S_MISC + MS_W4);
    float* sX  = (float*)(smem + S_MISC + MS_X);
    float* sT  = (float*)(smem + S_MISC + MS_T);
    int*   sIdx = (int*)(smem + S_MISC + MS_IDX);
    float* sPart = (float*)(smem + S_MISC + MS_PART);

    // Prefetch W1 both chunks into the two stages.
    cp_issue32k(sb + S_W0, g_w1_hi[dom][0], tid); CP_COMMIT();
    cp_issue32k(sb + S_W1, g_w1_hi[dom][1], tid); CP_COMMIT();

    if (tid < TILE_M) {
        if (tid < nm) {
            int i = g_idx[dom * N_MAX + base_pt + tid];
            sIdx[tid] = i; sX[tid] = x[i]; sT[tid] = t[i];
        } else { sIdx[tid] = -1; sX[tid] = 0.0f; sT[tid] = 0.0f; }
        sBx[tid] = (tid < FDIM) ? Bf[(dom * FDIM + tid) * 2]     : 0.0f;
        sBt[tid] = (tid < FDIM) ? Bf[(dom * FDIM + tid) * 2 + 1] : 0.0f;
        sB1[tid] = b1[dom * HDIM + tid];
        sB2[tid] = b2[dom * HDIM + tid];
        sB3[tid] = b3[dom * HDIM + tid];
        sW4[tid] = W4[dom * HDIM + tid];
    }
    __syncthreads();

    float acc[4][4][4];
#pragma unroll
    for (int s = 0; s < 4; s++)
#pragma unroll
        for (int u = 0; u < 4; u++)
#pragma unroll
            for (int r = 0; r < 4; r++) acc[s][u][r] = 0.0f;

    // ---- layer 1, K chunk 0 (W1c0 in stage0) ----
    gen_feats(smem, sBx, sBt, sX, sT, 0, tid);
    CP_WAIT(1);
    __syncthreads();
    mma_pass(acc, sb, S_W0, m0, n0, lane);
    __syncthreads();
    // ---- layer 1, K chunk 1 (feats in place; W2 -> stage0) ----
    gen_feats(smem, sBx, sBt, sX, sT, 1, tid);
    cp_issue32k(sb + S_W0, g_w2_hi[dom], tid); CP_COMMIT();
    CP_WAIT(1);
    __syncthreads();
    mma_pass(acc, sb, S_W1, m0, n0, lane);
    __syncthreads();
    // ---- layer 2 (W2 in stage0; W3 -> stage1) ----
    epilogue(acc, smem, sB1, m0, n0, lane);
    cp_issue32k(sb + S_W1, g_w3_hi[dom], tid); CP_COMMIT();
    CP_WAIT(1);
    __syncthreads();
    mma_pass(acc, sb, S_W0, m0, n0, lane);
    __syncthreads();
    // ---- layer 3 (W3 in stage1) ----
    epilogue(acc, smem, sB2, m0, n0, lane);
    CP_WAIT(0);
    __syncthreads();
    mma_pass(acc, sb, S_W1, m0, n0, lane);
    __syncthreads();

    // ---- head: p = sum_n silu(z3 + b3[n]) * W4[n] ----
    {
        const int lr = lane >> 2, lc = (lane & 3) * 2;
        float hp[4][2];
#pragma unroll
        for (int s = 0; s < 4; s++) { hp[s][0] = 0.0f; hp[s][1] = 0.0f; }
#pragma unroll
        for (int s = 0; s < 4; s++)
#pragma unroll
            for (int u = 0; u < 4; u++) {
                int n_ = n0 + u * 8 + lc;
                float w0 = sW4[n_], w1 = sW4[n_ + 1];
                float b0 = sB3[n_], b1v = sB3[n_ + 1];
                hp[s][0] += silu_f(acc[s][u][0] + b0) * w0 + silu_f(acc[s][u][1] + b1v) * w1;
                hp[s][1] += silu_f(acc[s][u][2] + b0) * w0 + silu_f(acc[s][u][3] + b1v) * w1;
            }
#pragma unroll
        for (int off = 1; off <= 2; off <<= 1)
#pragma unroll
            for (int s = 0; s < 4; s++) {
                hp[s][0] += __shfl_xor_sync(0xFFFFFFFF, hp[s][0], off);
                hp[s][1] += __shfl_xor_sync(0xFFFFFFFF, hp[s][1], off);
            }
        if ((lane & 3) == 0)
#pragma unroll
            for (int s = 0; s < 4; s++) {
                sPart[wn * TILE_M + m0 + s * 16 + lr]     = hp[s][0];
                sPart[wn * TILE_M + m0 + s * 16 + lr + 8] = hp[s][1];
            }
    }
    __syncthreads();
    if (tid < nm)
        out[sIdx[tid]] = sPart[tid] + sPart[TILE_M + tid]
                       + sPart[2 * TILE_M + tid] + sPart[3 * TILE_M + tid] + b4[dom];
}

// ---------------- launch ----------------
extern "C" void kernel_launch(void* const* d_in, const int* in_sizes, int n_in,
                              void* d_out, int out_size) {
    const float* x  = (const float*)d_in[0];
    const float* t  = (const float*)d_in[1];
    const float* Bf = (const float*)d_in[2];
    const float* W1 = (const float*)d_in[3];
    const float* b1 = (const float*)d_in[4];
    const float* W2 = (const float*)d_in[5];
    const float* b2 = (const float*)d_in[6];
    const float* W3 = (const float*)d_in[7];
    const float* b3 = (const float*)d_in[8];
    const float* W4 = (const float*)d_in[9];
    const float* b4 = (const float*)d_in[10];
    float* out = (float*)d_out;
    const int n = in_sizes[0];
    (void)n_in; (void)out_size;

    cudaFuncSetAttribute(xpinn_mma_kernel,
                         cudaFuncAttributeMaxDynamicSharedMemorySize, SMEM_TOTAL);

    zero_counts_kernel<<<1, 32>>>();
    bucket_kernel<<<(n + 255) / 256, 256>>>(x, n);
    {
        const int total = DNUM * 2 * HDIM * HDIM + 2 * DNUM * HDIM * HDIM;
        prep_weights_kernel<<<(total + 255) / 256, 256>>>(W1, W2, W3);
    }
    dim3 grid((n + TILE_M - 1) / TILE_M, DNUM);
    xpinn_mma_kernel<<<grid, NT, SMEM_TOTAL>>>(x, t, Bf, b1, b2, b3, W4, b4, out);
}